// round 15
// baseline (speedup 1.0000x reference)
#include <cuda_runtime.h>
#include <cuda_bf16.h>

// SoftRankNDCGLoss: B=128, L=1024
//
// s_i = f(p_i), f(x) = sum_j erf((x - p_j)/2)  (Gaussian-smoothed ECDF).
// Build f on a FIXED M=16 grid [-5.6, 5.6], tanh-cubic erf approx (HW tanh,
// packed f32x2); grid loop reads the row from L1. Grade ballots after the
// loop (hides target load). idcg computed by warps 16-31 in the phase-2 slot.
// Interp weights + gain hoisted BEFORE bar1 so the post-bar2 critical path is
// minimal. Per-row ndcg accumulated via global float atomic; last CTA's
// leader writes -acc/B (acq_rel counter, no threadfence).

constexpr int BATCH = 128;
constexpr int LEN   = 1024;
constexpr int M     = 16;               // grid points per row
constexpr int SUBS  = LEN / M;          // 64 j-chunks
constexpr int TPB   = 1024;

constexpr float GLO   = -5.6f;
constexpr float GHI   =  5.6f;
constexpr float GH    = (GHI - GLO) / (float)(M - 4);   // grid step
constexpr float GINVH = (float)(M - 4) / (GHI - GLO);

__device__ float    g_acc  = 0.0f;
__device__ unsigned g_done = 0;

typedef unsigned long long ull;

__device__ __forceinline__ ull pack2(float lo, float hi) {
    ull r; asm("mov.b64 %0, {%1, %2};" : "=l"(r) : "f"(lo), "f"(hi)); return r;
}
__device__ __forceinline__ void unpack2(ull v, float& lo, float& hi) {
    asm("mov.b64 {%0, %1}, %2;" : "=f"(lo), "=f"(hi) : "l"(v));
}
__device__ __forceinline__ ull add2(ull a, ull b) {
    ull r; asm("add.rn.f32x2 %0, %1, %2;" : "=l"(r) : "l"(a), "l"(b)); return r;
}
__device__ __forceinline__ ull mul2(ull a, ull b) {
    ull r; asm("mul.rn.f32x2 %0, %1, %2;" : "=l"(r) : "l"(a), "l"(b)); return r;
}
__device__ __forceinline__ ull fma2(ull a, ull b, ull c) {
    ull r; asm("fma.rn.f32x2 %0, %1, %2, %3;" : "=l"(r) : "l"(a), "l"(b), "l"(c)); return r;
}
__device__ __forceinline__ float tanh_fast(float x) {
    float r; asm("tanh.approx.f32 %0, %1;" : "=f"(r) : "f"(x)); return r;
}
__device__ __forceinline__ float warp_sum(float v) {
    #pragma unroll
    for (int o = 16; o > 0; o >>= 1)
        v += __shfl_down_sync(0xFFFFFFFFu, v, o);
    return v;
}
// butterfly reduce: result in ALL lanes
__device__ __forceinline__ ull warp_sum_u64_all(ull v) {
    #pragma unroll
    for (int o = 16; o > 0; o >>= 1)
        v += __shfl_xor_sync(0xFFFFFFFFu, v, o);
    return v;
}
// fetch-add with acq_rel gpu scope: releases this CTA's prior global writes,
// and (for the winner) acquires all earlier CTAs' released writes.
__device__ __forceinline__ unsigned atom_inc_acqrel(unsigned* p) {
    unsigned old;
    asm volatile("atom.acq_rel.gpu.global.add.u32 %0, [%1], 1;"
                 : "=r"(old) : "l"(p) : "memory");
    return old;
}

__global__ __launch_bounds__(TPB, 1) void ndcg_kernel(
    const float* __restrict__ preds,
    const float* __restrict__ target,
    float* __restrict__ out)
{
    __shared__ float spart[SUBS][M + 1];           // grid partials (padded)
    __shared__ float sg[M];                        // grid f values
    __shared__ float sred[32];                     // dcg warp partials
    __shared__ ull   swcnt[32];                    // per-warp packed counts
    __shared__ float s_idcg;                       // row idcg (atomic combine)

    const int b    = blockIdx.x;
    const int tid  = threadIdx.x;
    const int lane = tid & 31;
    const int warp = tid >> 5;

    const float pi = preds[b * LEN + tid];         // warms L1 with the row
    const float ti = target[b * LEN + tid];        // overlapped by the loop
    if (tid == 0) s_idcg = 0.0f;

    // ---- hoisted interp weights + gain (depend only on pi / ti; computed
    //      here so the post-bar2 path is just LDS + FMA + log2 + div) ----
    const float u  = (pi - GLO) * GINVH + 1.5f;
    int m = (int)floorf(u);
    m = min(max(m, 1), M - 3);
    const float tf = u - (float)m;
    const float ta = tf - 1.0f;
    const float tb = tf - 2.0f;
    const float tc = tf + 1.0f;
    const float wm1 = -tf * ta * tb * (1.0f / 6.0f);
    const float w0  =  tc * ta * tb * 0.5f;
    const float w1  = -tc * tf * tb * 0.5f;
    const float w2  =  tc * tf * ta * (1.0f / 6.0f);
    const int   gi   = (int)ti;
    const float gain = (float)((1 << gi) - 1);     // grades are integer 0..4

    // ---- build f on the fixed grid: point m_pt, j-chunk sub ----
    // tanh is odd: accumulate tanh(poly(p_j - x)) and negate the sum.
    const int m_pt = tid & (M - 1);
    const int sub  = tid >> 4;                     // 0..63
    const float x  = GLO + ((float)m_pt - 1.5f) * GH;

    const float A = 0.5641896f;
    const float B = 0.0126140f;
    const ull nx2 = pack2(-x, -x);
    const ull A2  = pack2(A, A);
    const ull B2  = pack2(B, B);

    const float4* p4 = reinterpret_cast<const float4*>(preds + b * LEN);
    float s0 = 0.0f, s1 = 0.0f;
    const int base4 = sub * (M / 4);               // 4 float4 = 16 elems
    #pragma unroll
    for (int k = 0; k < M / 4; ++k) {
        const float4 v = __ldg(&p4[base4 + k]);    // LDG.128, L1 hit
        const ull va = pack2(v.x, v.y);
        const ull vb = pack2(v.z, v.w);
        #pragma unroll
        for (int q = 0; q < 2; ++q) {
            ull d  = add2(q ? vb : va, nx2);       // p_j - x
            ull dd = mul2(d, d);
            ull uu = fma2(dd, B2, A2);
            ull t  = mul2(d, uu);
            float t0, t1; unpack2(t, t0, t1);
            s0 += tanh_fast(t0);
            s1 += tanh_fast(t1);
        }
    }
    spart[sub][m_pt] = -(s0 + s1);                 // negate: f uses x - p_j

    // ---- per-warp grade counts (after the loop: target load fully hidden) ----
    {
        unsigned b1 = __ballot_sync(0xFFFFFFFFu, gi == 1);
        unsigned b2 = __ballot_sync(0xFFFFFFFFu, gi == 2);
        unsigned b3 = __ballot_sync(0xFFFFFFFFu, gi == 3);
        unsigned b4 = __ballot_sync(0xFFFFFFFFu, gi == 4);
        if (lane == 0) {
            ull pk = (ull)__popc(b1)
                   | ((ull)__popc(b2) << 16)
                   | ((ull)__popc(b3) << 32)
                   | ((ull)__popc(b4) << 48);
            swcnt[warp] = pk;
        }
    }
    __syncthreads();   // bar1: orders spart + swcnt + s_idcg init

    // ---- phase 2 (parallel):
    //   warps 0..15 : reduce grid point w -> sg[w]
    //   warps 16..31: grade counts (butterfly), idcg terms for 64 ranks each,
    //                 combined into s_idcg via smem atomic (16 adds)
    if (warp < M) {
        float g = spart[lane][warp] + spart[lane + 32][warp];  // padded: conflict-free
        g = warp_sum(g);
        if (lane == 0) sg[warp] = g;
    } else {
        const ull v = warp_sum_u64_all(swcnt[lane]);   // fields < 1024: no carry
        const int c4 = (int)((v >> 48) & 0xFFFFu);
        const int c3 = c4 + (int)((v >> 32) & 0xFFFFu);
        const int c2 = c3 + (int)((v >> 16) & 0xFFFFu);
        const int c1 = c2 + (int)( v        & 0xFFFFu);
        float id_i = 0.0f;
        #pragma unroll
        for (int q = 0; q < 2; ++q) {
            const int r = (warp - 16) * 64 + q * 32 + lane;   // descending rank
            const int g = (r < c4) ? 4 : (r < c3) ? 3 : (r < c2) ? 2 : (r < c1) ? 1 : 0;
            id_i += __fdividef((float)((1 << g) - 1), __log2f((float)(r + 2)));
        }
        id_i = warp_sum(id_i);
        if (lane == 0) atomicAdd(&s_idcg, id_i);   // 16 adds, off critical path
    }
    __syncthreads();   // bar2: publishes sg + s_idcg

    // ---- minimal post-bar2 path: 4 LDS + 4 FMA + log2 + div ----
    const float f = wm1 * sg[m - 1] + w0 * sg[m] + w1 * sg[m + 1] + w2 * sg[m + 2];
    const float er = 512.5f + 0.5f * f;            // 1 + (L-1)/2 + 0.5*f
    float dcg_i = __fdividef(gain, __log2f(er + 1.0f));

    // ---- single-value block reduction of dcg ----
    dcg_i = warp_sum(dcg_i);
    if (lane == 0) sred[warp] = dcg_i;
    __syncthreads();   // bar3

    if (warp == 0) {
        float d = sred[lane];
        #pragma unroll
        for (int o = 16; o > 0; o >>= 1)
            d += __shfl_down_sync(0xFFFFFFFFu, d, o);
        if (lane == 0) {
            const float ndcg_b = d / (s_idcg + 1e-10f);
            atomicAdd(&g_acc, ndcg_b);             // fire-and-forget (RED)
            unsigned old = atom_inc_acqrel(&g_done);   // release the add
            if (old == (unsigned)(gridDim.x - 1)) {
                // winner: all 128 adds are visible (acquire)
                float acc = *((volatile float*)&g_acc);
                out[0] = -acc / (float)BATCH;
                g_acc  = 0.0f;          // reset for next graph replay
                g_done = 0u;
            }
        }
    }
}

extern "C" void kernel_launch(void* const* d_in, const int* in_sizes, int n_in,
                              void* d_out, int out_size)
{
    const float* preds  = (const float*)d_in[0];
    const float* target = (const float*)d_in[1];
    float* out = (float*)d_out;

    ndcg_kernel<<<BATCH, TPB>>>(preds, target, out);
}

// round 16
// speedup vs baseline: 1.0295x; 1.0295x over previous
#include <cuda_runtime.h>
#include <cuda_bf16.h>

// SoftRankNDCGLoss: B=128, L=1024   — converged configuration (R14 winner)
//
// s_i = f(p_i), f(x) = sum_j erf((x - p_j)/2)  (Gaussian-smoothed ECDF).
// Build f on a FIXED M=16 grid [-5.6, 5.6], tanh-cubic erf approx (HW tanh,
// packed f32x2); grid loop reads the row from L1. Grade ballots run AFTER
// the loop (hides the target DRAM load). idcg computed by warps 16-31 in the
// phase-2 slot and combined via smem atomics, so the terminal path reduces
// only dcg. Per-row ndcg accumulated with a global float atomic; last CTA's
// leader writes -acc/B (acq_rel counter, no threadfence).

constexpr int BATCH = 128;
constexpr int LEN   = 1024;
constexpr int M     = 16;               // grid points per row
constexpr int SUBS  = LEN / M;          // 64 j-chunks
constexpr int TPB   = 1024;

constexpr float GLO   = -5.6f;
constexpr float GHI   =  5.6f;
constexpr float GH    = (GHI - GLO) / (float)(M - 4);   // grid step
constexpr float GINVH = (float)(M - 4) / (GHI - GLO);

__device__ float    g_acc  = 0.0f;
__device__ unsigned g_done = 0;

typedef unsigned long long ull;

__device__ __forceinline__ ull pack2(float lo, float hi) {
    ull r; asm("mov.b64 %0, {%1, %2};" : "=l"(r) : "f"(lo), "f"(hi)); return r;
}
__device__ __forceinline__ void unpack2(ull v, float& lo, float& hi) {
    asm("mov.b64 {%0, %1}, %2;" : "=f"(lo), "=f"(hi) : "l"(v));
}
__device__ __forceinline__ ull add2(ull a, ull b) {
    ull r; asm("add.rn.f32x2 %0, %1, %2;" : "=l"(r) : "l"(a), "l"(b)); return r;
}
__device__ __forceinline__ ull mul2(ull a, ull b) {
    ull r; asm("mul.rn.f32x2 %0, %1, %2;" : "=l"(r) : "l"(a), "l"(b)); return r;
}
__device__ __forceinline__ ull fma2(ull a, ull b, ull c) {
    ull r; asm("fma.rn.f32x2 %0, %1, %2, %3;" : "=l"(r) : "l"(a), "l"(b), "l"(c)); return r;
}
__device__ __forceinline__ float tanh_fast(float x) {
    float r; asm("tanh.approx.f32 %0, %1;" : "=f"(r) : "f"(x)); return r;
}
__device__ __forceinline__ float warp_sum(float v) {
    #pragma unroll
    for (int o = 16; o > 0; o >>= 1)
        v += __shfl_down_sync(0xFFFFFFFFu, v, o);
    return v;
}
// butterfly reduce: result in ALL lanes
__device__ __forceinline__ ull warp_sum_u64_all(ull v) {
    #pragma unroll
    for (int o = 16; o > 0; o >>= 1)
        v += __shfl_xor_sync(0xFFFFFFFFu, v, o);
    return v;
}
// fetch-add with acq_rel gpu scope: releases this CTA's prior global writes,
// and (for the winner) acquires all earlier CTAs' released writes.
__device__ __forceinline__ unsigned atom_inc_acqrel(unsigned* p) {
    unsigned old;
    asm volatile("atom.acq_rel.gpu.global.add.u32 %0, [%1], 1;"
                 : "=r"(old) : "l"(p) : "memory");
    return old;
}

__global__ __launch_bounds__(TPB, 1) void ndcg_kernel(
    const float* __restrict__ preds,
    const float* __restrict__ target,
    float* __restrict__ out)
{
    __shared__ float spart[SUBS][M + 1];           // grid partials (padded)
    __shared__ float sg[M];                        // grid f values
    __shared__ float sred[32];                     // dcg warp partials
    __shared__ ull   swcnt[32];                    // per-warp packed counts
    __shared__ float s_idcg;                       // row idcg (atomic combine)

    const int b    = blockIdx.x;
    const int tid  = threadIdx.x;
    const int lane = tid & 31;
    const int warp = tid >> 5;

    const float pi = preds[b * LEN + tid];         // warms L1 with the row
    const float ti = target[b * LEN + tid];        // overlapped by the loop
    if (tid == 0) s_idcg = 0.0f;

    // ---- build f on the fixed grid: point m_pt, j-chunk sub ----
    // tanh is odd: accumulate tanh(poly(p_j - x)) and negate the sum.
    const int m_pt = tid & (M - 1);
    const int sub  = tid >> 4;                     // 0..63
    const float x  = GLO + ((float)m_pt - 1.5f) * GH;

    const float A = 0.5641896f;
    const float B = 0.0126140f;
    const ull nx2 = pack2(-x, -x);
    const ull A2  = pack2(A, A);
    const ull B2  = pack2(B, B);

    const float4* p4 = reinterpret_cast<const float4*>(preds + b * LEN);
    float s0 = 0.0f, s1 = 0.0f;
    const int base4 = sub * (M / 4);               // 4 float4 = 16 elems
    #pragma unroll
    for (int k = 0; k < M / 4; ++k) {
        const float4 v = __ldg(&p4[base4 + k]);    // LDG.128, L1 hit
        const ull va = pack2(v.x, v.y);
        const ull vb = pack2(v.z, v.w);
        #pragma unroll
        for (int q = 0; q < 2; ++q) {
            ull d  = add2(q ? vb : va, nx2);       // p_j - x
            ull dd = mul2(d, d);
            ull u  = fma2(dd, B2, A2);
            ull t  = mul2(d, u);
            float t0, t1; unpack2(t, t0, t1);
            s0 += tanh_fast(t0);
            s1 += tanh_fast(t1);
        }
    }
    spart[sub][m_pt] = -(s0 + s1);                 // negate: f uses x - p_j

    // ---- per-warp grade counts (AFTER the loop: target load fully hidden) ----
    const int gi = (int)ti;
    {
        unsigned b1 = __ballot_sync(0xFFFFFFFFu, gi == 1);
        unsigned b2 = __ballot_sync(0xFFFFFFFFu, gi == 2);
        unsigned b3 = __ballot_sync(0xFFFFFFFFu, gi == 3);
        unsigned b4 = __ballot_sync(0xFFFFFFFFu, gi == 4);
        if (lane == 0) {
            ull pk = (ull)__popc(b1)
                   | ((ull)__popc(b2) << 16)
                   | ((ull)__popc(b3) << 32)
                   | ((ull)__popc(b4) << 48);
            swcnt[warp] = pk;
        }
    }
    __syncthreads();   // bar1: orders spart + swcnt + s_idcg init

    // ---- phase 2 (parallel):
    //   warps 0..15 : reduce grid point w -> sg[w]
    //   warps 16..31: grade counts (butterfly), idcg terms for 64 ranks each,
    //                 combined into s_idcg via smem atomic (16 adds)
    if (warp < M) {
        float g = spart[lane][warp] + spart[lane + 32][warp];  // padded: conflict-free
        g = warp_sum(g);
        if (lane == 0) sg[warp] = g;
    } else {
        const ull v = warp_sum_u64_all(swcnt[lane]);   // fields < 1024: no carry
        const int c4 = (int)((v >> 48) & 0xFFFFu);
        const int c3 = c4 + (int)((v >> 32) & 0xFFFFu);
        const int c2 = c3 + (int)((v >> 16) & 0xFFFFu);
        const int c1 = c2 + (int)( v        & 0xFFFFu);
        float id_i = 0.0f;
        #pragma unroll
        for (int q = 0; q < 2; ++q) {
            const int r = (warp - 16) * 64 + q * 32 + lane;   // descending rank
            const int g = (r < c4) ? 4 : (r < c3) ? 3 : (r < c2) ? 2 : (r < c1) ? 1 : 0;
            id_i += __fdividef((float)((1 << g) - 1), __log2f((float)(r + 2)));
        }
        id_i = warp_sum(id_i);
        if (lane == 0) atomicAdd(&s_idcg, id_i);   // 16 adds, off critical path
    }
    __syncthreads();   // bar2: publishes sg + s_idcg

    // ---- cubic Lagrange interpolation of f at p_i ----
    const float u  = (pi - GLO) * GINVH + 1.5f;
    int m = (int)floorf(u);
    m = min(max(m, 1), M - 3);
    const float tf = u - (float)m;
    const float ta = tf - 1.0f;
    const float tb = tf - 2.0f;
    const float tc = tf + 1.0f;
    const float wm1 = -tf * ta * tb * (1.0f / 6.0f);
    const float w0  =  tc * ta * tb * 0.5f;
    const float w1  = -tc * tf * tb * 0.5f;
    const float w2  =  tc * tf * ta * (1.0f / 6.0f);
    const float f = wm1 * sg[m - 1] + w0 * sg[m] + w1 * sg[m + 1] + w2 * sg[m + 2];

    const float er   = 512.5f + 0.5f * f;          // 1 + (L-1)/2 + 0.5*f
    const float gain = (float)((1 << gi) - 1);     // grades are integer 0..4
    float dcg_i = __fdividef(gain, __log2f(er + 1.0f));

    // ---- single-value block reduction of dcg ----
    dcg_i = warp_sum(dcg_i);
    if (lane == 0) sred[warp] = dcg_i;
    __syncthreads();   // bar3

    if (warp == 0) {
        float d = sred[lane];
        #pragma unroll
        for (int o = 16; o > 0; o >>= 1)
            d += __shfl_down_sync(0xFFFFFFFFu, d, o);
        if (lane == 0) {
            const float ndcg_b = d / (s_idcg + 1e-10f);
            atomicAdd(&g_acc, ndcg_b);             // fire-and-forget (RED)
            unsigned old = atom_inc_acqrel(&g_done);   // release the add
            if (old == (unsigned)(gridDim.x - 1)) {
                // winner: all 128 adds are visible (acquire)
                float acc = *((volatile float*)&g_acc);
                out[0] = -acc / (float)BATCH;
                g_acc  = 0.0f;          // reset for next graph replay
                g_done = 0u;
            }
        }
    }
}

extern "C" void kernel_launch(void* const* d_in, const int* in_sizes, int n_in,
                              void* d_out, int out_size)
{
    const float* preds  = (const float*)d_in[0];
    const float* target = (const float*)d_in[1];
    float* out = (float*)d_out;

    ndcg_kernel<<<BATCH, TPB>>>(preds, target, out);
}